// round 5
// baseline (speedup 1.0000x reference)
#include <cuda_runtime.h>
#include <math.h>

#define NSTEPS 8760
#define NGRID  2048
#define NMUL   2
#define LENF   72
#define DTC    (1.0f/24.0f)

// Scratch (device globals: no allocation allowed in kernel_launch)
__device__ float g_q[NSTEPS * NGRID];   // mul-averaged discharge [t][g]
__device__ float g_w[LENF * NGRID];     // gamma weights [k][g]

__device__ __forceinline__ float flg2(float x) {
    float y; asm("lg2.approx.f32 %0, %1;" : "=f"(y) : "f"(x)); return y;
}
__device__ __forceinline__ float fex2(float x) {
    float y; asm("ex2.approx.f32 %0, %1;" : "=f"(y) : "f"(x)); return y;
}

// ---------------------------------------------------------------------------
// Stage 1: HBV scan. ONE thread per grid cell, running BOTH mul-chains
// interleaved (they share forcing). 2048 threads; chain stalls of one chain
// are filled by the other chain's independent instruction stream.
// ---------------------------------------------------------------------------
__global__ void __launch_bounds__(64) hbv_scan_kernel(
    const float* __restrict__ prcp,
    const float* __restrict__ tmean,
    const float* __restrict__ pet,
    const float* __restrict__ phy)
{
    const int g = blockIdx.x * 64 + threadIdx.x;     // 0..2047

    const float lbv[19] = {1.0f, 50.0f, 0.05f, 0.01f, 0.001f, 0.2f, 0.0f, 0.0f,
                           -2.5f, 0.5f, 0.0f, 0.0f, 0.3f, 0.0f, 0.0f, 0.0f,
                           5.0f/DTC, 0.0f, 0.5f};
    const float ubv[19] = {6.0f, 1000.0f, 0.9f, 0.5f, 0.2f, 1.0f, 10.0f, 100.0f,
                           2.5f, 10.0f, 0.1f, 0.2f, 5.0f, 1.0f, 20.0f, 2500.0f,
                           120.0f/DTC, 1.0f, 5.0f};

    float BETA[2], FC[2], UZL[2], TTp[2], CWH[2], BETAET[2], Cc[2], ALPHA[2],
          invFC[2], k0dt[2], k1dt[2], k2dt[2], percdt[2],
          cfmaxdt[2], cfrcfmaxdt[2], fmin_f0dt[2], omfmin_f0dt[2], evap_c[2];
#pragma unroll
    for (int m = 0; m < 2; m++) {
        float pp[19];
#pragma unroll
        for (int i = 0; i < 19; i++) {
            float r = phy[g * (19 * NMUL) + i * NMUL + m];
            pp[i] = lbv[i] + r * (ubv[i] - lbv[i]);
        }
        BETA[m]   = pp[0];
        FC[m]     = pp[1];
        UZL[m]    = pp[7];
        TTp[m]    = pp[8];
        CWH[m]    = pp[11];
        BETAET[m] = pp[12];
        Cc[m]     = pp[13];
        ALPHA[m]  = pp[18];
        invFC[m]  = 1.0f / pp[1];
        k0dt[m]   = pp[2] * DTC;
        k1dt[m]   = pp[3] * DTC;
        k2dt[m]   = pp[4] * DTC;
        percdt[m] = pp[6] * DTC;
        cfmaxdt[m]    = pp[9] * DTC;
        cfrcfmaxdt[m] = pp[10] * cfmaxdt[m];
        float f0dt    = pp[16] * DTC;
        fmin_f0dt[m]   = pp[17] * f0dt;
        omfmin_f0dt[m] = (1.0f - pp[17]) * f0dt;
        evap_c[m]      = pp[12] * flg2(1.0f / (pp[5] * pp[1]));
    }

    float SP[2], MW[2], SM[2], SUZ[2], SLZ[2], CcSLZ[2];
#pragma unroll
    for (int m = 0; m < 2; m++) {
        SP[m] = MW[m] = SM[m] = SUZ[m] = SLZ[m] = 0.001f;
        CcSLZ[m] = Cc[m] * 0.001f;
    }

    // one timestep: both chains, returns mul-mean Q
    auto step = [&](float P, float T, float PV) -> float {
        float Qs = 0.0f;
#pragma unroll
        for (int m = 0; m < 2; m++) {
            // snow (short, mostly parallel chain)
            float SNOW = (T < TTp[m]) ? P : 0.0f;
            float RAIN = P - SNOW;
            float SP1  = SP[m] + SNOW;
            float melt = fminf(fmaxf(cfmaxdt[m] * (T - TTp[m]), 0.0f), SP1);
            float MW1  = MW[m] + melt;
            float SP2  = SP1 - melt;
            float refr = fminf(fmaxf(cfrcfmaxdt[m] * (TTp[m] - T), 0.0f), MW1);
            SP[m] = SP2 + refr;
            float MW2    = MW1 - refr;
            float tosoil = fmaxf(fmaf(-CWH[m], SP[m], MW2), 0.0f);
            MW[m] = MW2 - tosoil;
            float win = RAIN + tosoil;

            // soil moisture (critical carry cycle)
            float ratio = SM[m] * invFC[m];
            float omr   = fmaxf(1.0f - ratio, 1e-6f);
            float fcap  = fmaf(omfmin_f0dt[m], fex2(ALPHA[m] * flg2(omr)),
                               fmin_f0dt[m]);
            float infil = fminf(win, fcap);
            float soilw = fminf(fex2(BETA[m] * flg2(ratio)), 1.0f);
            float SM1   = fmaf(infil, 1.0f - soilw, SM[m]);
            float SM2   = fminf(SM1, FC[m]);
            float e     = fex2(fmaf(flg2(SM2), BETAET[m], evap_c[m]));
            float x     = fminf(PV * e, PV);          // PV * min(e,1)
            float SM3   = fmaxf(SM2 - x, 1e-5f);      // max(SM2 - AET, 1e-5)
            float w1    = fmaf(-invFC[m], SM3, 1.0f); // 1 - SM3/FC, in [0,1]
            float cap   = CcSLZ[m] * w1;
            SM[m] = SM3 + cap;

            // zones (off the SM-chain)
            float rech = infil * soilw;
            float excs = SM1 - SM2;
            float surf = win - infil;
            float SUZ1 = SUZ[m] + (rech + excs) + surf;
            float perc = fminf(SUZ1, percdt[m]);
            float SUZ2 = SUZ1 - perc;
            float Q0   = k0dt[m] * fmaxf(SUZ2 - UZL[m], 0.0f);
            float SUZ3 = SUZ2 - Q0;
            float Q1   = k1dt[m] * SUZ3;
            SUZ[m] = SUZ3 - Q1;
            float SLZ1 = (SLZ[m] - cap) + perc;
            float Q2   = k2dt[m] * SLZ1;
            SLZ[m] = SLZ1 - Q2;
            CcSLZ[m] = Cc[m] * SLZ[m];
            Qs += Q0 + Q1 + Q2;
        }
        return 0.5f * Qs;
    };

    // forcing pipeline: blocks of 4 steps, prefetch distance = 8 steps
    float Pb[4], Tb[4], Eb[4], Pn[4], Tn[4], En[4];
#pragma unroll
    for (int u = 0; u < 4; u++) {
        Pb[u] = prcp [u * NGRID + g];
        Tb[u] = tmean[u * NGRID + g];
        Eb[u] = pet  [u * NGRID + g];
        Pn[u] = prcp [(4 + u) * NGRID + g];
        Tn[u] = tmean[(4 + u) * NGRID + g];
        En[u] = pet  [(4 + u) * NGRID + g];
    }

    for (int t0 = 0; t0 < NSTEPS; t0 += 4) {
        const int tp = min(t0 + 8, NSTEPS - 4);
        float Pf[4], Tf[4], Ef[4];
#pragma unroll
        for (int u = 0; u < 4; u++) {
            Pf[u] = prcp [(tp + u) * NGRID + g];
            Tf[u] = tmean[(tp + u) * NGRID + g];
            Ef[u] = pet  [(tp + u) * NGRID + g];
        }
#pragma unroll
        for (int u = 0; u < 4; u++)
            g_q[(t0 + u) * NGRID + g] = step(Pb[u], Tb[u], Eb[u]);
#pragma unroll
        for (int u = 0; u < 4; u++) {
            Pb[u] = Pn[u]; Tb[u] = Tn[u]; Eb[u] = En[u];
            Pn[u] = Pf[u]; Tn[u] = Tf[u]; En[u] = Ef[u];
        }
    }
}

// ---------------------------------------------------------------------------
// Stage 2: gamma routing weights, one thread per grid.
// ---------------------------------------------------------------------------
__global__ void __launch_bounds__(128) weights_kernel(const float* __restrict__ distr)
{
    int g = blockIdx.x * blockDim.x + threadIdx.x;
    if (g >= NGRID) return;

    float aa  = fmaxf(distr[g * 3 + 0] * 5.0f,  0.0f) + 0.1f;
    float th  = fmaxf(distr[g * 3 + 1] * 12.0f, 0.0f) + 0.5f;
    float tau = distr[g * 3 + 2] * 48.0f;

    float lga   = lgammaf(aa);
    float lth   = logf(th);
    float invth = 1.0f / th;
    float am1   = aa - 1.0f;

    float ws[LENF];
    float s = 0.0f;
#pragma unroll
    for (int k = 0; k < LENF; k++) {
        float t  = (float)k + 0.5f;
        float ts = fmaxf(t - tau, 0.001f);
        float lw = -lga - aa * lth + am1 * logf(ts) - ts * invth;
        float w  = expf(lw);
        ws[k] = w;
        s += w;
    }
    float inv = 1.0f / s;
#pragma unroll
    for (int k = 0; k < LENF; k++)
        g_w[k * NGRID + g] = ws[k] * inv;
}

// ---------------------------------------------------------------------------
// Stage 3: 72-tap causal FIR (coalesced [t][g] reads, register ring).
// ---------------------------------------------------------------------------
#define CONV_GT   32
#define CONV_TT   64
#define CONV_RPT  8

__global__ void __launch_bounds__(256) conv_kernel(float* __restrict__ out)
{
    __shared__ float q_sh[CONV_TT + LENF - 1][CONV_GT];   // 135 x 32
    __shared__ float w_sh[LENF][CONV_GT];                 // 72 x 32

    const int tid   = threadIdx.x;
    const int gbase = blockIdx.x * CONV_GT;
    const int t0    = blockIdx.y * CONV_TT;

    for (int idx = tid; idx < (CONV_TT + LENF - 1) * CONV_GT; idx += 256) {
        int j = idx >> 5, c = idx & 31;
        int tq = t0 - (LENF - 1) + j;
        float v = 0.0f;
        if (tq >= 0 && tq < NSTEPS) v = g_q[tq * NGRID + gbase + c];
        q_sh[j][c] = v;
    }
    for (int idx = tid; idx < LENF * CONV_GT; idx += 256) {
        int k = idx >> 5, c = idx & 31;
        w_sh[k][c] = g_w[k * NGRID + gbase + c];
    }
    __syncthreads();

    const int tx   = tid & 31;
    const int ty   = tid >> 5;        // 0..7
    const int trow = ty * CONV_RPT;

    float acc[CONV_RPT];
#pragma unroll
    for (int r = 0; r < CONV_RPT; r++) acc[r] = 0.0f;

    float buf[CONV_RPT];              // mod-8 register rolling window
#pragma unroll
    for (int i = 0; i < CONV_RPT; i++)
        buf[(LENF - 1 + i) & 7] = q_sh[trow + LENF - 1 + i][tx];

#pragma unroll
    for (int k = 0; k < LENF; k++) {
        float wv = w_sh[k][tx];
#pragma unroll
        for (int r = 0; r < CONV_RPT; r++)
            acc[r] += wv * buf[(LENF - 1 - k + r) & 7];
        if (k < LENF - 1)
            buf[(LENF - 2 - k) & 7] = q_sh[trow + LENF - 2 - k][tx];
    }

#pragma unroll
    for (int r = 0; r < CONV_RPT; r++) {
        int t = t0 + trow + r;
        if (t < NSTEPS)
            out[t * NGRID + gbase + tx] = acc[r];
    }
}

// ---------------------------------------------------------------------------
extern "C" void kernel_launch(void* const* d_in, const int* in_sizes, int n_in,
                              void* d_out, int out_size)
{
    const float* prcp  = (const float*)d_in[0];
    const float* tmean = (const float*)d_in[1];
    const float* pet   = (const float*)d_in[2];
    const float* phy   = (const float*)d_in[3];
    const float* distr = (const float*)d_in[4];
    float* out = (float*)d_out;

    hbv_scan_kernel<<<NGRID / 64, 64>>>(prcp, tmean, pet, phy);
    weights_kernel<<<(NGRID + 127) / 128, 128>>>(distr);

    dim3 gc(NGRID / CONV_GT, (NSTEPS + CONV_TT - 1) / CONV_TT);
    conv_kernel<<<gc, 256>>>(out);
}

// round 6
// speedup vs baseline: 1.3786x; 1.3786x over previous
#include <cuda_runtime.h>
#include <math.h>

#define NSTEPS 8760
#define NGRID  2048
#define NMUL   2
#define NTID   (NGRID*NMUL)
#define LENF   72
#define DTC    (1.0f/24.0f)
#define NBLK   (NSTEPS/4)      /* 2190 four-step blocks; 2190 = 3*730 */

// Scratch (device globals: no allocation allowed in kernel_launch)
__device__ float g_q2[NSTEPS * NTID];   // per-(t, grid, mul) discharge [t][tid]
__device__ float g_w[LENF * NGRID];     // gamma weights [k][g]

__device__ __forceinline__ float flg2(float x) {
    float y; asm("lg2.approx.f32 %0, %1;" : "=f"(y) : "f"(x)); return y;
}
__device__ __forceinline__ float fex2(float x) {
    float y; asm("ex2.approx.f32 %0, %1;" : "=f"(y) : "f"(x)); return y;
}

// ---------------------------------------------------------------------------
// Stage 1: HBV scan, software-pipelined: snow(t+1) braided with soil/zones(t).
// One thread per (grid, mul); 4096 threads in 128 blocks of 32.
// ---------------------------------------------------------------------------
__global__ void __launch_bounds__(32) hbv_scan_kernel(
    const float* __restrict__ prcp,
    const float* __restrict__ tmean,
    const float* __restrict__ pet,
    const float* __restrict__ phy)
{
    const int tid = blockIdx.x * 32 + threadIdx.x;   // 0..4095
    const int g = tid >> 1;
    const int m = tid & 1;

    const float lbv[19] = {1.0f, 50.0f, 0.05f, 0.01f, 0.001f, 0.2f, 0.0f, 0.0f,
                           -2.5f, 0.5f, 0.0f, 0.0f, 0.3f, 0.0f, 0.0f, 0.0f,
                           5.0f/DTC, 0.0f, 0.5f};
    const float ubv[19] = {6.0f, 1000.0f, 0.9f, 0.5f, 0.2f, 1.0f, 10.0f, 100.0f,
                           2.5f, 10.0f, 0.1f, 0.2f, 5.0f, 1.0f, 20.0f, 2500.0f,
                           120.0f/DTC, 1.0f, 5.0f};
    float pp[19];
#pragma unroll
    for (int i = 0; i < 19; i++) {
        float r = phy[g * (19 * NMUL) + i * NMUL + m];
        pp[i] = lbv[i] + r * (ubv[i] - lbv[i]);
    }
    const float BETA   = pp[0];
    const float FC     = pp[1];
    const float UZL    = pp[7];
    const float TTp    = pp[8];
    const float CWH    = pp[11];
    const float BETAET = pp[12];
    const float Cc     = pp[13];
    const float ALPHA  = pp[18];

    const float invFC       = 1.0f / FC;
    const float k0dt        = pp[2] * DTC;
    const float k1dt        = pp[3] * DTC;
    const float k2dt        = pp[4] * DTC;
    const float percdt      = pp[6] * DTC;
    const float cfmaxdt     = pp[9] * DTC;
    const float cfrcfmaxdt  = pp[10] * cfmaxdt;
    const float f0dt        = pp[16] * DTC;
    const float fmin_f0dt   = pp[17] * f0dt;
    const float omfmin_f0dt = (1.0f - pp[17]) * f0dt;
    const float evap_c      = BETAET * flg2(1.0f / (pp[5] * FC));
    // evapfactor at SM=FC, clipped to 1:  min((1/LP)^BETAET, 1)
    const float eFCc        = fminf(fex2(BETAET * flg2(1.0f / pp[5])), 1.0f);

    float SP = 0.001f, MW = 0.001f, SM = 0.001f, SUZ = 0.001f, SLZ = 0.001f;
    float CcSLZ = Cc * 0.001f;

    // snow stage for one step: updates SP/MW, returns water_in
    auto snow_stage = [&](float P, float T) -> float {
        float SNOW = (T < TTp) ? P : 0.0f;
        float RAIN = P - SNOW;
        float SP1  = SP + SNOW;
        float melt = fminf(fmaxf(cfmaxdt * (T - TTp), 0.0f), SP1);
        float MW1  = MW + melt;
        float SP2  = SP1 - melt;
        float refr = fminf(fmaxf(cfrcfmaxdt * (TTp - T), 0.0f), MW1);
        SP = SP2 + refr;
        float MW2    = MW1 - refr;
        float tosoil = fmaxf(fmaf(-CWH, SP, MW2), 0.0f);
        MW = MW2 - tosoil;
        return RAIN + tosoil;
    };

    // soil + zones for one step: consumes win, updates SM/SUZ/SLZ, returns q
    auto soil_stage = [&](float win, float PV) -> float {
        float ratio = SM * invFC;
        float omr   = fmaxf(1.0f - ratio, 1e-6f);
        float fcap  = fmaf(omfmin_f0dt, fex2(ALPHA * flg2(omr)), fmin_f0dt);
        float infil = fminf(win, fcap);
        float soilw = fminf(fex2(BETA * flg2(ratio)), 1.0f);
        float SM1   = fmaf(infil, 1.0f - soilw, SM);
        float SM2   = fminf(SM1, FC);
        // monotonicity: evapfactor(min(SM1,FC)) = min(e_raw(SM1), e_raw(FC))
        float e1    = fex2(fmaf(flg2(SM1), BETAET, evap_c));
        float x     = fminf(PV * e1, PV * eFCc);
        float SM3   = fmaxf(SM2 - x, 1e-5f);
        float w1    = fmaf(-invFC, SM3, 1.0f);
        float cap   = CcSLZ * w1;
        SM = SM3 + cap;

        float rech = infil * soilw;
        float excs = SM1 - SM2;
        float surf = win - infil;
        float SUZ1 = SUZ + (rech + excs) + surf;
        float perc = fminf(SUZ1, percdt);
        float SUZ2 = SUZ1 - perc;
        float Q0   = k0dt * fmaxf(SUZ2 - UZL, 0.0f);
        float SUZ3 = SUZ2 - Q0;
        float Q1   = k1dt * SUZ3;
        SUZ = SUZ3 - Q1;
        float SLZ1 = (SLZ - cap) + perc;
        float Q2   = k2dt * SLZ1;
        SLZ = SLZ1 - Q2;
        CcSLZ = Cc * SLZ;
        return Q0 + Q1 + Q2;
    };

    // forcing: triple-buffered 4-step blocks, MOV-free rotation via unroll-3,
    // prefetch lookahead = 2 blocks (8 steps).
    float Pf[3][4], Tf[3][4], Ef[3][4];
#pragma unroll
    for (int s = 0; s < 2; s++)
#pragma unroll
        for (int u = 0; u < 4; u++) {
            Pf[s][u] = prcp [(s * 4 + u) * NGRID + g];
            Tf[s][u] = tmean[(s * 4 + u) * NGRID + g];
            Ef[s][u] = pet  [(s * 4 + u) * NGRID + g];
        }

    // pipeline prologue: snow(0)
    float win_cur = snow_stage(Pf[0][0], Tf[0][0]);

    float* qbase = g_q2 + tid;

    for (int it = 0; it < NBLK / 3; it++) {
        const int b0 = it * 3;
#pragma unroll
        for (int s = 0; s < 3; s++) {
            const int blk = b0 + s;
            const int pb  = min(blk + 2, NBLK - 1);
            const int ps  = (s + 2) % 3;
            const int s1  = (s + 1) % 3;
            // prefetch block blk+2 into the slot consumed 2 blocks ago
#pragma unroll
            for (int u = 0; u < 4; u++) {
                Pf[ps][u] = prcp [(pb * 4 + u) * NGRID + g];
                Tf[ps][u] = tmean[(pb * 4 + u) * NGRID + g];
                Ef[ps][u] = pet  [(pb * 4 + u) * NGRID + g];
            }
            const int t0 = blk * 4;
#pragma unroll
            for (int u = 0; u < 4; u++) {
                // snow(t+1): independent of soil/zones(t) — braided by ptxas.
                // At the global last step this reads stale data; result unused.
                float win_next = (u < 3) ? snow_stage(Pf[s][u + 1], Tf[s][u + 1])
                                         : snow_stage(Pf[s1][0],    Tf[s1][0]);
                float q = soil_stage(win_cur, Ef[s][u]);
                qbase[(size_t)(t0 + u) * NTID] = q;
                win_cur = win_next;
            }
        }
    }
}

// ---------------------------------------------------------------------------
// Stage 2: gamma routing weights, one thread per grid.
// ---------------------------------------------------------------------------
__global__ void __launch_bounds__(128) weights_kernel(const float* __restrict__ distr)
{
    int g = blockIdx.x * blockDim.x + threadIdx.x;
    if (g >= NGRID) return;

    float aa  = fmaxf(distr[g * 3 + 0] * 5.0f,  0.0f) + 0.1f;
    float th  = fmaxf(distr[g * 3 + 1] * 12.0f, 0.0f) + 0.5f;
    float tau = distr[g * 3 + 2] * 48.0f;

    float lga   = lgammaf(aa);
    float lth   = logf(th);
    float invth = 1.0f / th;
    float am1   = aa - 1.0f;

    float ws[LENF];
    float s = 0.0f;
#pragma unroll
    for (int k = 0; k < LENF; k++) {
        float t  = (float)k + 0.5f;
        float ts = fmaxf(t - tau, 0.001f);
        float lw = -lga - aa * lth + am1 * logf(ts) - ts * invth;
        float w  = expf(lw);
        ws[k] = w;
        s += w;
    }
    float inv = 1.0f / s;
#pragma unroll
    for (int k = 0; k < LENF; k++)
        g_w[k * NGRID + g] = ws[k] * inv;
}

// ---------------------------------------------------------------------------
// Stage 3: 72-tap causal FIR; mul-pair averaged at load via float2.
// ---------------------------------------------------------------------------
#define CONV_GT   32
#define CONV_TT   64
#define CONV_RPT  8

__global__ void __launch_bounds__(256) conv_kernel(float* __restrict__ out)
{
    __shared__ float q_sh[CONV_TT + LENF - 1][CONV_GT];   // 135 x 32
    __shared__ float w_sh[LENF][CONV_GT];                 // 72 x 32

    const int tid   = threadIdx.x;
    const int gbase = blockIdx.x * CONV_GT;
    const int t0    = blockIdx.y * CONV_TT;

    const float2* q2 = reinterpret_cast<const float2*>(g_q2);

    for (int idx = tid; idx < (CONV_TT + LENF - 1) * CONV_GT; idx += 256) {
        int j = idx >> 5, c = idx & 31;
        int tq = t0 - (LENF - 1) + j;
        float v = 0.0f;
        if (tq >= 0 && tq < NSTEPS) {
            float2 p = q2[(size_t)tq * NGRID + gbase + c];
            v = 0.5f * (p.x + p.y);
        }
        q_sh[j][c] = v;
    }
    for (int idx = tid; idx < LENF * CONV_GT; idx += 256) {
        int k = idx >> 5, c = idx & 31;
        w_sh[k][c] = g_w[k * NGRID + gbase + c];
    }
    __syncthreads();

    const int tx   = tid & 31;
    const int ty   = tid >> 5;        // 0..7
    const int trow = ty * CONV_RPT;

    float acc[CONV_RPT];
#pragma unroll
    for (int r = 0; r < CONV_RPT; r++) acc[r] = 0.0f;

    float buf[CONV_RPT];              // mod-8 register rolling window
#pragma unroll
    for (int i = 0; i < CONV_RPT; i++)
        buf[(LENF - 1 + i) & 7] = q_sh[trow + LENF - 1 + i][tx];

#pragma unroll
    for (int k = 0; k < LENF; k++) {
        float wv = w_sh[k][tx];
#pragma unroll
        for (int r = 0; r < CONV_RPT; r++)
            acc[r] += wv * buf[(LENF - 1 - k + r) & 7];
        if (k < LENF - 1)
            buf[(LENF - 2 - k) & 7] = q_sh[trow + LENF - 2 - k][tx];
    }

#pragma unroll
    for (int r = 0; r < CONV_RPT; r++) {
        int t = t0 + trow + r;
        if (t < NSTEPS)
            out[t * NGRID + gbase + tx] = acc[r];
    }
}

// ---------------------------------------------------------------------------
extern "C" void kernel_launch(void* const* d_in, const int* in_sizes, int n_in,
                              void* d_out, int out_size)
{
    const float* prcp  = (const float*)d_in[0];
    const float* tmean = (const float*)d_in[1];
    const float* pet   = (const float*)d_in[2];
    const float* phy   = (const float*)d_in[3];
    const float* distr = (const float*)d_in[4];
    float* out = (float*)d_out;

    hbv_scan_kernel<<<NTID / 32, 32>>>(prcp, tmean, pet, phy);
    weights_kernel<<<(NGRID + 127) / 128, 128>>>(distr);

    dim3 gc(NGRID / CONV_GT, (NSTEPS + CONV_TT - 1) / CONV_TT);
    conv_kernel<<<gc, 256>>>(out);
}

// round 7
// speedup vs baseline: 2.1753x; 1.5779x over previous
#include <cuda_runtime.h>
#include <math.h>

#define NSTEPS 8760
#define NGRID  2048
#define NMUL   2
#define NTID   (NGRID*NMUL)
#define LENF   72
#define DTC    (1.0f/24.0f)

// Scratch (device globals: no allocation allowed in kernel_launch)
__device__ float g_q2[NSTEPS * NTID];   // per-(t, grid, mul) discharge [t][tid]
__device__ float g_w[LENF * NGRID];     // gamma weights [k][g]

__device__ __forceinline__ float flg2(float x) {
    float y; asm("lg2.approx.f32 %0, %1;" : "=f"(y) : "f"(x)); return y;
}
__device__ __forceinline__ float fex2(float x) {
    float y; asm("ex2.approx.f32 %0, %1;" : "=f"(y) : "f"(x)); return y;
}

// ---------------------------------------------------------------------------
// Stage 1: HBV scan. One thread per (grid, mul); 4096 threads, R2 layout,
// instruction-dieted step body (~65 SASS instrs/step).
// ---------------------------------------------------------------------------
__global__ void __launch_bounds__(128) hbv_scan_kernel(
    const float* __restrict__ prcp,
    const float* __restrict__ tmean,
    const float* __restrict__ pet,
    const float* __restrict__ phy)
{
    const int tid = blockIdx.x * 128 + threadIdx.x;   // 0..4095
    const int g = tid >> 1;
    const int m = tid & 1;

    const float lbv[19] = {1.0f, 50.0f, 0.05f, 0.01f, 0.001f, 0.2f, 0.0f, 0.0f,
                           -2.5f, 0.5f, 0.0f, 0.0f, 0.3f, 0.0f, 0.0f, 0.0f,
                           5.0f/DTC, 0.0f, 0.5f};
    const float ubv[19] = {6.0f, 1000.0f, 0.9f, 0.5f, 0.2f, 1.0f, 10.0f, 100.0f,
                           2.5f, 10.0f, 0.1f, 0.2f, 5.0f, 1.0f, 20.0f, 2500.0f,
                           120.0f/DTC, 1.0f, 5.0f};
    float pp[19];
#pragma unroll
    for (int i = 0; i < 19; i++) {
        float r = phy[g * (19 * NMUL) + i * NMUL + m];
        pp[i] = lbv[i] + r * (ubv[i] - lbv[i]);
    }
    const float BETA   = pp[0];
    const float FC     = pp[1];
    const float CFR    = pp[10];
    const float CWH    = pp[11];
    const float BETAET = pp[12];
    const float Cc     = pp[13];
    const float ALPHA  = pp[18];

    const float invFC       = 1.0f / FC;
    const float k0dt        = pp[2] * DTC;
    const float k1dt        = pp[3] * DTC;
    const float k2dt        = pp[4] * DTC;
    const float percdt      = pp[6] * DTC;
    const float cfmaxdt     = pp[9] * DTC;
    const float f0dt        = pp[16] * DTC;
    const float fmin_f0dt   = pp[17] * f0dt;
    const float omfmin_f0dt = (1.0f - pp[17]) * f0dt;
    const float evap_c      = BETAET * flg2(1.0f / (pp[5] * FC));
    // e at SM=FC, clipped at 1: min((1/LP)^BETAET, 1)
    const float eFCc        = fminf(fex2(BETAET * flg2(1.0f / pp[5])), 1.0f);
    // snow constants: mp = cfmaxdt*T - mpc  (mpc = cfmaxdt*TT folded)
    const float mpc         = cfmaxdt * pp[8];
    // zone constants
    const float ck0         = 1.0f - k0dt;       // SUZ3 = min(SUZ2, ck0*SUZ2 + k0uzl)
    const float k0uzl       = k0dt * pp[7];
    const float c1          = 1.0f - k1dt;       // SUZ' = c1*SUZ3
    const float c2          = 1.0f - k2dt;       // SLZ' = c2*SLZ1
    const float cc2         = Cc * c2;           // CcSLZ' = cc2*SLZ1

    float SP = 0.001f, MW = 0.001f, SM = 0.001f, SUZ = 0.001f, SLZ = 0.001f;
    float CcSLZ = Cc * 0.001f;

    auto step = [&](float P, float T, float PV) -> float {
        // --- snow: signed transfer x = melt - refreeze (mutually exclusive)
        float mp    = fmaf(cfmaxdt, T, -mpc);            // cfmaxdt*(T-TT)
        float SNOW  = (mp < 0.0f) ? P : 0.0f;
        float RAIN  = P - SNOW;
        float SP1   = SP + SNOW;
        float cfrmp = CFR * mp;
        float a     = fminf(fmaxf(mp, 0.0f), SP1);       // melt
        float b     = fmaxf(fminf(cfrmp, 0.0f), -MW);    // -refreeze
        float x     = a + b;
        SP = SP1 - x;
        float MW2    = MW + x;
        float tosoil = fmaxf(fmaf(-CWH, SP, MW2), 0.0f);
        MW = MW2 - tosoil;
        float win = RAIN + tosoil;

        // --- soil moisture (critical carry cycle)
        float omr   = fmaxf(fmaf(-invFC, SM, 1.0f), 1e-6f);
        float fcap  = fmaf(omfmin_f0dt, fex2(ALPHA * flg2(omr)), fmin_f0dt);
        float infil = fminf(win, fcap);
        float ratio = SM * invFC;
        float soilw = fminf(fex2(BETA * flg2(ratio)), 1.0f);
        float SM1   = fmaf(infil, 1.0f - soilw, SM);
        float SM2   = fminf(SM1, FC);
        float e1    = fex2(fmaf(flg2(SM1), BETAET, evap_c));  // e_raw(SM1)
        float xe    = fminf(PV * e1, PV * eFCc);              // PV * e(SM2) clipped
        float SM3   = fmaxf(SM2 - xe, 1e-5f);
        float w1    = fmaf(-invFC, SM3, 1.0f);
        float cap   = CcSLZ * w1;
        SM = SM3 + cap;

        // --- zones (compressed): inflow = win + SM_old - SM2
        float tws  = win + (ratio * FC);                  // win + SM (re-derive SM)
        float SUZ1 = SUZ + (tws - SM2);
        float SUZ2 = fmaxf(SUZ1 - percdt, 0.0f);
        float perc = SUZ1 - SUZ2;
        float SUZ3 = fminf(SUZ2, fmaf(ck0, SUZ2, k0uzl));
        float SUZn = c1 * SUZ3;
        SUZ = SUZn;
        float SLZ1 = (SLZ - cap) + perc;
        float Q2   = k2dt * SLZ1;
        SLZ   = c2 * SLZ1;
        CcSLZ = cc2 * SLZ1;
        return (SUZ2 - SUZn) + Q2;                        // Q0+Q1+Q2
    };

    const int U = 8;                     // 8760 % 8 == 0
    float Pb[U], Tb[U], Eb[U];
#pragma unroll
    for (int u = 0; u < U; u++) {
        Pb[u] = prcp [u * NGRID + g];
        Tb[u] = tmean[u * NGRID + g];
        Eb[u] = pet  [u * NGRID + g];
    }

    float* qbase = g_q2 + tid;

    for (int t0 = 0; t0 < NSTEPS - U; t0 += U) {
        float Pn[U], Tn[U], En[U];
        const int t1 = t0 + U;
#pragma unroll
        for (int u = 0; u < U; u++) {
            Pn[u] = prcp [(t1 + u) * NGRID + g];
            Tn[u] = tmean[(t1 + u) * NGRID + g];
            En[u] = pet  [(t1 + u) * NGRID + g];
        }
#pragma unroll
        for (int u = 0; u < U; u++)
            qbase[(size_t)(t0 + u) * NTID] = step(Pb[u], Tb[u], Eb[u]);
#pragma unroll
        for (int u = 0; u < U; u++) { Pb[u] = Pn[u]; Tb[u] = Tn[u]; Eb[u] = En[u]; }
    }
    // peeled last block (no prefetch, no branch in main loop)
#pragma unroll
    for (int u = 0; u < U; u++)
        qbase[(size_t)(NSTEPS - U + u) * NTID] = step(Pb[u], Tb[u], Eb[u]);
}

// ---------------------------------------------------------------------------
// Stage 2: gamma routing weights, one thread per grid.
// ---------------------------------------------------------------------------
__global__ void __launch_bounds__(128) weights_kernel(const float* __restrict__ distr)
{
    int g = blockIdx.x * blockDim.x + threadIdx.x;
    if (g >= NGRID) return;

    float aa  = fmaxf(distr[g * 3 + 0] * 5.0f,  0.0f) + 0.1f;
    float th  = fmaxf(distr[g * 3 + 1] * 12.0f, 0.0f) + 0.5f;
    float tau = distr[g * 3 + 2] * 48.0f;

    float lga   = lgammaf(aa);
    float lth   = logf(th);
    float invth = 1.0f / th;
    float am1   = aa - 1.0f;

    float ws[LENF];
    float s = 0.0f;
#pragma unroll
    for (int k = 0; k < LENF; k++) {
        float t  = (float)k + 0.5f;
        float ts = fmaxf(t - tau, 0.001f);
        float lw = -lga - aa * lth + am1 * logf(ts) - ts * invth;
        float w  = expf(lw);
        ws[k] = w;
        s += w;
    }
    float inv = 1.0f / s;
#pragma unroll
    for (int k = 0; k < LENF; k++)
        g_w[k * NGRID + g] = ws[k] * inv;
}

// ---------------------------------------------------------------------------
// Stage 3: 72-tap causal FIR. Tile 32 grids x 128 timesteps (halo 1.55x);
// 16 outputs/thread, mod-16 register rolling window. Mul pair averaged at
// load via float2 (g_q2 is [t][tid], tid = 2g+m).
// ---------------------------------------------------------------------------
#define CONV_GT   32
#define CONV_TT   128
#define CONV_RPT  16
#define CONV_QS   (CONV_TT + LENF - 1)   /* 199 */

__global__ void __launch_bounds__(256) conv_kernel(float* __restrict__ out)
{
    __shared__ float q_sh[CONV_QS][CONV_GT];   // 199 x 32
    __shared__ float w_sh[LENF][CONV_GT];      // 72 x 32

    const int tid   = threadIdx.x;
    const int gbase = blockIdx.x * CONV_GT;
    const int t0    = blockIdx.y * CONV_TT;

    const float2* q2 = reinterpret_cast<const float2*>(g_q2);

    for (int idx = tid; idx < CONV_QS * CONV_GT; idx += 256) {
        int j = idx >> 5, c = idx & 31;
        int tq = t0 - (LENF - 1) + j;
        float v = 0.0f;
        if (tq >= 0 && tq < NSTEPS) {
            float2 p = q2[(size_t)tq * NGRID + gbase + c];
            v = 0.5f * (p.x + p.y);
        }
        q_sh[j][c] = v;
    }
    for (int idx = tid; idx < LENF * CONV_GT; idx += 256) {
        int k = idx >> 5, c = idx & 31;
        w_sh[k][c] = g_w[k * NGRID + gbase + c];
    }
    __syncthreads();

    const int tx   = tid & 31;
    const int ty   = tid >> 5;        // 0..7
    const int trow = ty * CONV_RPT;

    float acc[CONV_RPT];
#pragma unroll
    for (int r = 0; r < CONV_RPT; r++) acc[r] = 0.0f;

    float buf[16];                    // mod-16 register rolling window
#pragma unroll
    for (int i = 0; i < 16; i++)
        buf[(LENF - 1 + i) & 15] = q_sh[trow + LENF - 1 + i][tx];

#pragma unroll
    for (int k = 0; k < LENF; k++) {
        float wv = w_sh[k][tx];
#pragma unroll
        for (int r = 0; r < CONV_RPT; r++)
            acc[r] += wv * buf[(LENF - 1 - k + r) & 15];
        if (k < LENF - 1)
            buf[(LENF - 2 - k) & 15] = q_sh[trow + LENF - 2 - k][tx];
    }

#pragma unroll
    for (int r = 0; r < CONV_RPT; r++) {
        int t = t0 + trow + r;
        if (t < NSTEPS)
            out[t * NGRID + gbase + tx] = acc[r];
    }
}

// ---------------------------------------------------------------------------
extern "C" void kernel_launch(void* const* d_in, const int* in_sizes, int n_in,
                              void* d_out, int out_size)
{
    const float* prcp  = (const float*)d_in[0];
    const float* tmean = (const float*)d_in[1];
    const float* pet   = (const float*)d_in[2];
    const float* phy   = (const float*)d_in[3];
    const float* distr = (const float*)d_in[4];
    float* out = (float*)d_out;

    hbv_scan_kernel<<<NTID / 128, 128>>>(prcp, tmean, pet, phy);
    weights_kernel<<<(NGRID + 127) / 128, 128>>>(distr);

    dim3 gc(NGRID / CONV_GT, (NSTEPS + CONV_TT - 1) / CONV_TT);
    conv_kernel<<<gc, 256>>>(out);
}